// round 8
// baseline (speedup 1.0000x reference)
#include <cuda_runtime.h>
#include <cuda_bf16.h>
#include <cstdint>

// out[b,f] = -2.5*log10( sum_l A[b,l] * (trans[f,l]*w[l]) )
// wt_kernel -> g_wt bf16 [F,L] (2MB, L2-resident)
// gemm_log_kernel: 256 thr, warp tile 32x32 (2Mx4N), BK=128, grid 128.
//   A: LDG reg-prefetch depth 2 -> bf16 convert -> smem (no fp32 smem staging).
//   B: 3-stage cp.async. Fragments double-buffered (ldmatrix ks+1 || mma ks).
// No split-K (regressed twice). tcgen05 unavailable (ptxas targets compute_103).

#define BM 64
#define BN 128
#define BK 128
#define THREADS 256
#define B_ST   32768                  // BN*BK*2
#define ABF_ST 16384                  // BM*BK*2
#define OFF_ABF (3 * B_ST)
#define DYN_SMEM (OFF_ABF + 2 * ABF_ST + 1024)

__device__ __align__(16) __nv_bfloat16 g_wt[128 * 8192];

__global__ void wt_kernel(const float* __restrict__ trans,
                          const float* __restrict__ lam, int F, int L) {
    int i4 = blockIdx.x * blockDim.x + threadIdx.x;
    int total = (F * L) >> 2;
    if (i4 >= total) return;
    int l0 = (i4 % (L >> 2)) << 2;
    float4 t = reinterpret_cast<const float4*>(trans)[i4];
    float w[4];
#pragma unroll
    for (int j = 0; j < 4; j++) {
        int l = l0 + j;
        int hi = l + 1 < L ? l + 1 : L - 1;
        int lo = l > 0 ? l - 1 : 0;
        w[j] = 0.5f * (__ldg(lam + hi) - __ldg(lam + lo));
    }
    __nv_bfloat162 p0 = __floats2bfloat162_rn(t.x * w[0], t.y * w[1]);
    __nv_bfloat162 p1 = __floats2bfloat162_rn(t.z * w[2], t.w * w[3]);
    uint2 v = { reinterpret_cast<uint32_t&>(p0), reinterpret_cast<uint32_t&>(p1) };
    reinterpret_cast<uint2*>(g_wt)[i4] = v;
}

__device__ __forceinline__ uint32_t smem_u32(const void* p) {
    uint32_t a;
    asm("{ .reg .u64 t; cvta.to.shared.u64 t, %1; cvt.u32.u64 %0, t; }"
        : "=r"(a) : "l"(p));
    return a;
}
__device__ __forceinline__ void ldmx4(uint32_t* r, uint32_t addr) {
    asm volatile("ldmatrix.sync.aligned.m8n8.x4.shared.b16 {%0,%1,%2,%3}, [%4];\n"
                 : "=r"(r[0]), "=r"(r[1]), "=r"(r[2]), "=r"(r[3]) : "r"(addr));
}
__device__ __forceinline__ void mma16816(float* c, const uint32_t* a, const uint32_t* b) {
    asm volatile("mma.sync.aligned.m16n8k16.row.col.f32.bf16.bf16.f32 "
                 "{%0,%1,%2,%3}, {%4,%5,%6,%7}, {%8,%9}, {%0,%1,%2,%3};\n"
                 : "+f"(c[0]), "+f"(c[1]), "+f"(c[2]), "+f"(c[3])
                 : "r"(a[0]), "r"(a[1]), "r"(a[2]), "r"(a[3]), "r"(b[0]), "r"(b[1]));
}
__device__ __forceinline__ uint32_t packbf2(float x, float y) {
    __nv_bfloat162 h = __floats2bfloat162_rn(x, y);
    return reinterpret_cast<uint32_t&>(h);
}
__device__ __forceinline__ void cp16(uint32_t dst, const void* src) {
    asm volatile("cp.async.cg.shared.global [%0], [%1], 16;"
                 :: "r"(dst), "l"(src) : "memory");
}
#define CP_COMMIT() asm volatile("cp.async.commit_group;" ::: "memory")
#define CP_WAIT1()  asm volatile("cp.async.wait_group 1;" ::: "memory")

__global__ void __launch_bounds__(THREADS, 1)
gemm_log_kernel(const float* __restrict__ A, float* __restrict__ out, int K) {
    extern __shared__ char dynsmem[];
    const uint32_t base = (smem_u32(dynsmem) + 1023) & ~1023u;
    const uint32_t bB   = base;
    const uint32_t bAbf = base + OFF_ABF;

    const int tid  = threadIdx.x;
    const int lane = tid & 31;
    const int warp = tid >> 5;
    const size_t bm0 = (size_t)blockIdx.x * BM;
    const int NKT = K / BK;              // 64

    // ---- A LDG mapping: row ar = tid>>2 (0..63), 32 fp32 cols at 32*(tid&3)
    const int ar = tid >> 2, acg = tid & 3;
    const float4* aSrc4 = reinterpret_cast<const float4*>(A + (bm0 + ar) * (size_t)K)
                        + 8 * acg;
    // bf16 dest row: 256B = 16 chunks; this thread owns chunks 4*acg .. 4*acg+3
    uint32_t abfrel[4];
#pragma unroll
    for (int jj = 0; jj < 4; jj++)
        abfrel[jj] = (uint32_t)ar * 256 + (uint32_t)(((4 * acg + jj) ^ (ar & 7)) * 16);

    // ---- B cp mapping: 8 chunks/thread; row n (0..127), chunk cc (0..15)
    uint32_t brel[8];
    const __nv_bfloat16* bsrc[8];
#pragma unroll
    for (int j = 0; j < 8; j++) {
        int id = tid + 256 * j;
        int n = id >> 4, cc = id & 15;
        brel[j] = (uint32_t)n * 256 + (uint32_t)(((cc ^ (n & 7)) * 16));
        bsrc[j] = g_wt + (size_t)n * K + cc * 8;
    }

    // ---- warp grid: 2 M x 4 N, warp tile 32x32
    const int wmBase = (warp & 1) * 32;
    const int wnBase = (warp >> 1) * 32;
    int arow[2], brow[2];
#pragma unroll
    for (int mi = 0; mi < 2; mi++) arow[mi] = wmBase + mi * 16 + (lane & 15);
#pragma unroll
    for (int nj = 0; nj < 2; nj++) brow[nj] = wnBase + nj * 16 + ((lane >> 4) << 3) + (lane & 7);
    const int achalf = lane >> 4;
    const int bchalf = (lane >> 3) & 1;

    float acc[2][4][4];
#pragma unroll
    for (int i = 0; i < 2; i++)
#pragma unroll
        for (int j = 0; j < 4; j++)
#pragma unroll
            for (int k = 0; k < 4; k++) acc[i][j][k] = 0.f;

    float4 fa[2][8];   // A prefetch, two tiles in flight

#define LOAD_A(T) do {                                                        \
        const float4* _p = aSrc4 + (size_t)(T) * (BK >> 2);                   \
        float4* _d = fa[(T) & 1];                                             \
        _Pragma("unroll")                                                     \
        for (int _j = 0; _j < 8; _j++) _d[_j] = __ldg(_p + _j);               \
    } while (0)

#define CONVERT(T) do {                                                       \
        float4* _f = fa[(T) & 1];                                             \
        const uint32_t _da = bAbf + (uint32_t)(((T) & 1) ? ABF_ST : 0);       \
        _Pragma("unroll")                                                     \
        for (int _jj = 0; _jj < 4; _jj++) {                                   \
            float4 _x = _f[2 * _jj], _y = _f[2 * _jj + 1];                    \
            asm volatile("st.shared.v4.b32 [%0], {%1,%2,%3,%4};" ::           \
                "r"(_da + abfrel[_jj]),                                       \
                "r"(packbf2(_x.x, _x.y)), "r"(packbf2(_x.z, _x.w)),           \
                "r"(packbf2(_y.x, _y.y)), "r"(packbf2(_y.z, _y.w)) : "memory"); \
        }                                                                     \
    } while (0)

#define ISSUE_B(T, S) do {                                                    \
        const uint32_t _bd = bB + (uint32_t)(S) * B_ST;                       \
        _Pragma("unroll")                                                     \
        for (int _j = 0; _j < 8; _j++)                                        \
            cp16(_bd + brel[_j], bsrc[_j] + (size_t)(T) * BK);                \
    } while (0)

    // ---------- prologue ----------
    ISSUE_B(0, 0); CP_COMMIT();
    ISSUE_B(1, 1); CP_COMMIT();
    LOAD_A(0);
    LOAD_A(1);
    CONVERT(0);
    CP_WAIT1();               // B(0) complete
    __syncthreads();

    int sCur = 0, sIss = 2;

    // ---------- main loop: 1 barrier per 128-K tile ----------
    for (int kt = 0; kt < NKT; kt++) {
        if (kt + 2 < NKT) {
            LOAD_A(kt + 2);
            ISSUE_B(kt + 2, sIss);
        }
        CP_COMMIT();

        const uint32_t aoff = bAbf + (uint32_t)((kt & 1) ? ABF_ST : 0);
        const uint32_t boff = bB + (uint32_t)sCur * B_ST;

        uint32_t af[2][2][4], bf[2][2][4];   // fragment double buffer

#define LDFRAG(KS, BUF) do {                                                  \
        const int _ca = (KS) * 2 + achalf;                                    \
        const int _cb = (KS) * 2 + bchalf;                                    \
        _Pragma("unroll")                                                     \
        for (int _mi = 0; _mi < 2; _mi++)                                     \
            ldmx4(af[BUF][_mi],                                               \
                  aoff + (uint32_t)(arow[_mi] * 16 + (_ca ^ (arow[_mi] & 7))) * 16); \
        _Pragma("unroll")                                                     \
        for (int _nj = 0; _nj < 2; _nj++)                                     \
            ldmx4(bf[BUF][_nj],                                               \
                  boff + (uint32_t)(brow[_nj] * 16 + (_cb ^ (brow[_nj] & 7))) * 16); \
    } while (0)

        LDFRAG(0, 0);
#pragma unroll
        for (int ks = 0; ks < 8; ks++) {
            if (ks < 7) LDFRAG(ks + 1, (ks + 1) & 1);
            const int bu = ks & 1;
#pragma unroll
            for (int mi = 0; mi < 2; mi++)
#pragma unroll
                for (int nt = 0; nt < 4; nt++)
                    mma16816(acc[mi][nt], af[bu][mi], &bf[bu][nt >> 1][(nt & 1) * 2]);
        }
#undef LDFRAG

        if (kt + 1 < NKT) CONVERT(kt + 1);   // own data, no extra barrier needed
        CP_WAIT1();                          // B(kt+1) complete
        __syncthreads();                     // publish Abf[kt+1], B[kt+1]; free B[kt]

        sCur = (sCur == 2) ? 0 : sCur + 1;
        sIss = (sIss == 2) ? 0 : sIss + 1;
    }

    // ---------- epilogue: -2.5*log10(x) ----------
    const float C = -0.75257498915995302f;   // -2.5 / log2(10)
#pragma unroll
    for (int mi = 0; mi < 2; mi++) {
        const size_t row0 = bm0 + wmBase + mi * 16 + (lane >> 2);
#pragma unroll
        for (int nt = 0; nt < 4; nt++) {
            const int col = wnBase + nt * 8 + (lane & 3) * 2;
            float2 v0, v1;
            v0.x = C * __log2f(acc[mi][nt][0]);
            v0.y = C * __log2f(acc[mi][nt][1]);
            v1.x = C * __log2f(acc[mi][nt][2]);
            v1.y = C * __log2f(acc[mi][nt][3]);
            *reinterpret_cast<float2*>(out + row0 * BN + col)       = v0;
            *reinterpret_cast<float2*>(out + (row0 + 8) * BN + col) = v1;
        }
    }
}

extern "C" void kernel_launch(void* const* d_in, const int* in_sizes, int n_in,
                              void* d_out, int out_size) {
    const float* l_target = (const float*)d_in[0];   // [B, L] fp32
    const float* trans    = (const float*)d_in[1];   // [F, L] fp32
    const float* lam      = (const float*)d_in[2];   // [L]    fp32

    const int L = in_sizes[2];
    const int F = in_sizes[1] / L;   // 128
    const int B = in_sizes[0] / L;   // 8192
    float* out = (float*)d_out;

    cudaFuncSetAttribute(gemm_log_kernel,
                         cudaFuncAttributeMaxDynamicSharedMemorySize, DYN_SMEM);

    int total4 = (F * L) >> 2;
    wt_kernel<<<(total4 + 255) / 256, 256>>>(trans, lam, F, L);
    gemm_log_kernel<<<B / BM, THREADS, DYN_SMEM>>>(l_target, out, L);
}

// round 9
// speedup vs baseline: 1.5786x; 1.5786x over previous
#include <cuda_runtime.h>
#include <cuda_bf16.h>
#include <cstdint>

// out[b,f] = -2.5*log10( sum_l A[b,l] * (trans[f,l]*w[l]) )
// wt_kernel -> g_wt bf16 [F,L] (2MB, L2-resident)
// gemm_log_kernel: R5's conflict-free mma core (BM=64 BN=128 BK=64, 256 thr,
//   warp tile 32x32, 128B smem rows). A: LDG->reg->bf16->STS (no fp32 smem
//   roundtrip). B: 6-stage cp.async ring. ONE barrier per 2 k-tiles.
// Ruled out by measurement: split-K (2x), BK=128 / 256B rows (bank conflicts),
// manual fragment double-buffering (reg pressure). tcgen05 rejected by ptxas
// (compute_103 target).

#define BM 64
#define BN 128
#define BK 64
#define THREADS 256
#define B_ST   16384                 // BN*BK*2
#define ABF_ST 8192                  // BM*BK*2
#define NB_ST  6                     // B ring: 6 tiles (3 pairs)
#define OFF_ABF (NB_ST * B_ST)
#define DYN_SMEM (OFF_ABF + 4 * ABF_ST + 1024)   // 96 + 32 KB

__device__ __align__(16) __nv_bfloat16 g_wt[128 * 8192];

__global__ void wt_kernel(const float* __restrict__ trans,
                          const float* __restrict__ lam, int F, int L) {
    int i4 = blockIdx.x * blockDim.x + threadIdx.x;
    int total = (F * L) >> 2;
    if (i4 >= total) return;
    int l0 = (i4 % (L >> 2)) << 2;
    float4 t = reinterpret_cast<const float4*>(trans)[i4];
    float w[4];
#pragma unroll
    for (int j = 0; j < 4; j++) {
        int l = l0 + j;
        int hi = l + 1 < L ? l + 1 : L - 1;
        int lo = l > 0 ? l - 1 : 0;
        w[j] = 0.5f * (__ldg(lam + hi) - __ldg(lam + lo));
    }
    __nv_bfloat162 p0 = __floats2bfloat162_rn(t.x * w[0], t.y * w[1]);
    __nv_bfloat162 p1 = __floats2bfloat162_rn(t.z * w[2], t.w * w[3]);
    uint2 v = { reinterpret_cast<uint32_t&>(p0), reinterpret_cast<uint32_t&>(p1) };
    reinterpret_cast<uint2*>(g_wt)[i4] = v;
}

__device__ __forceinline__ uint32_t smem_u32(const void* p) {
    uint32_t a;
    asm("{ .reg .u64 t; cvta.to.shared.u64 t, %1; cvt.u32.u64 %0, t; }"
        : "=r"(a) : "l"(p));
    return a;
}
__device__ __forceinline__ void ldmx4(uint32_t* r, uint32_t addr) {
    asm volatile("ldmatrix.sync.aligned.m8n8.x4.shared.b16 {%0,%1,%2,%3}, [%4];\n"
                 : "=r"(r[0]), "=r"(r[1]), "=r"(r[2]), "=r"(r[3]) : "r"(addr));
}
__device__ __forceinline__ void mma16816(float* c, const uint32_t* a, const uint32_t* b) {
    asm volatile("mma.sync.aligned.m16n8k16.row.col.f32.bf16.bf16.f32 "
                 "{%0,%1,%2,%3}, {%4,%5,%6,%7}, {%8,%9}, {%0,%1,%2,%3};\n"
                 : "+f"(c[0]), "+f"(c[1]), "+f"(c[2]), "+f"(c[3])
                 : "r"(a[0]), "r"(a[1]), "r"(a[2]), "r"(a[3]), "r"(b[0]), "r"(b[1]));
}
__device__ __forceinline__ uint32_t packbf2(float x, float y) {
    __nv_bfloat162 h = __floats2bfloat162_rn(x, y);
    return reinterpret_cast<uint32_t&>(h);
}
__device__ __forceinline__ void cp16(uint32_t dst, const void* src) {
    asm volatile("cp.async.cg.shared.global [%0], [%1], 16;"
                 :: "r"(dst), "l"(src) : "memory");
}
#define CP_COMMIT() asm volatile("cp.async.commit_group;" ::: "memory")
#define CP_WAIT1()  asm volatile("cp.async.wait_group 1;" ::: "memory")

__global__ void __launch_bounds__(THREADS, 1)
gemm_log_kernel(const float* __restrict__ A, float* __restrict__ out, int K) {
    extern __shared__ char dynsmem[];
    const uint32_t base = (smem_u32(dynsmem) + 1023) & ~1023u;
    const uint32_t bB   = base;
    const uint32_t bAbf = base + OFF_ABF;

    const int tid  = threadIdx.x;
    const int lane = tid & 31;
    const int warp = tid >> 5;
    const size_t bm0 = (size_t)blockIdx.x * BM;
    const int NKT = K / BK;          // 128 tiles
    const int NP  = NKT >> 1;        // 64 pairs

    // ---- A LDG mapping: row ar = tid>>2 (0..63), 16 fp32 at cols 16*(tid&3)
    const int ar = tid >> 2, ac = tid & 3;
    const float4* aSrc4 = reinterpret_cast<const float4*>(A + (bm0 + ar) * (size_t)K)
                        + 4 * ac;
    // bf16 dest: 128B rows, chunks (2ac)^(ar&7), (2ac+1)^(ar&7)  (conflict-free)
    const uint32_t abfrel0 = (uint32_t)ar * 128 + (uint32_t)(((2 * ac)     ^ (ar & 7)) * 16);
    const uint32_t abfrel1 = (uint32_t)ar * 128 + (uint32_t)(((2 * ac + 1) ^ (ar & 7)) * 16);

    // ---- B cp mapping: 4 chunks/thread, 128B rows (conflict-free)
    uint32_t brel[4];
    const __nv_bfloat16* bsrc[4];
#pragma unroll
    for (int j = 0; j < 4; j++) {
        int id = tid + 256 * j;
        int n = id >> 3, cc = id & 7;
        brel[j] = (uint32_t)(n * 128 + ((cc ^ (n & 7)) * 16));
        bsrc[j] = g_wt + (size_t)n * K + cc * 8;
    }

    // ---- warp grid: 2 M x 4 N, warp tile 32x32 (R5 core)
    const int wmBase = (warp & 1) * 32;
    const int wnBase = (warp >> 1) * 32;
    int arow[2], brow[2];
#pragma unroll
    for (int mi = 0; mi < 2; mi++) arow[mi] = wmBase + mi * 16 + (lane & 15);
#pragma unroll
    for (int nj = 0; nj < 2; nj++) brow[nj] = wnBase + nj * 16 + ((lane >> 4) << 3) + (lane & 7);
    const int achalf = lane >> 4;
    const int bchalf = (lane >> 3) & 1;

    float acc[2][4][4];
#pragma unroll
    for (int i = 0; i < 2; i++)
#pragma unroll
        for (int j = 0; j < 4; j++)
#pragma unroll
            for (int k = 0; k < 4; k++) acc[i][j][k] = 0.f;

    float4 fa[2][4];   // one PAIR of A tiles in registers (2 tiles x 16 floats)

    // LDG pair P (tiles 2P, 2P+1) -> fa
#define LOAD_PAIR(P) do {                                                     \
        const float4* _p0 = aSrc4 + (size_t)(2 * (P)) * (BK >> 2);            \
        const float4* _p1 = _p0 + (BK >> 2);                                  \
        _Pragma("unroll")                                                     \
        for (int _j = 0; _j < 4; _j++) { fa[0][_j] = __ldg(_p0 + _j);         \
                                         fa[1][_j] = __ldg(_p1 + _j); }       \
    } while (0)

    // convert fa (pair P) -> A slots (2P)&3, (2P+1)&3
#define CONVERT_PAIR(P) do {                                                  \
        _Pragma("unroll")                                                     \
        for (int _t = 0; _t < 2; _t++) {                                      \
            const uint32_t _da = bAbf + (uint32_t)(((2 * (P) + _t) & 3)) * ABF_ST; \
            float4* _f = fa[_t];                                              \
            asm volatile("st.shared.v4.b32 [%0], {%1,%2,%3,%4};" ::           \
                "r"(_da + abfrel0),                                           \
                "r"(packbf2(_f[0].x, _f[0].y)), "r"(packbf2(_f[0].z, _f[0].w)), \
                "r"(packbf2(_f[1].x, _f[1].y)), "r"(packbf2(_f[1].z, _f[1].w)) : "memory"); \
            asm volatile("st.shared.v4.b32 [%0], {%1,%2,%3,%4};" ::           \
                "r"(_da + abfrel1),                                           \
                "r"(packbf2(_f[2].x, _f[2].y)), "r"(packbf2(_f[2].z, _f[2].w)), \
                "r"(packbf2(_f[3].x, _f[3].y)), "r"(packbf2(_f[3].z, _f[3].w)) : "memory"); \
        }                                                                     \
    } while (0)

    // cp.async B pair P into ring slots s0, s0+1 (one commit group)
#define ISSUE_B_PAIR(P, S0) do {                                              \
        const uint32_t _b0 = bB + (uint32_t)(S0) * B_ST;                      \
        const uint32_t _b1 = _b0 + B_ST;                                      \
        const size_t _o0 = (size_t)(2 * (P)) * BK;                            \
        _Pragma("unroll")                                                     \
        for (int _j = 0; _j < 4; _j++) {                                      \
            cp16(_b0 + brel[_j], bsrc[_j] + _o0);                             \
            cp16(_b1 + brel[_j], bsrc[_j] + _o0 + BK);                        \
        }                                                                     \
    } while (0)

    // compute one k-tile from A slot (uint32 offset) and B slot
#define COMPUTE_TILE(AOFF, BOFF) do {                                         \
        _Pragma("unroll")                                                     \
        for (int ks = 0; ks < 4; ks++) {                                      \
            uint32_t a[2][4], b[2][4];                                        \
            _Pragma("unroll")                                                 \
            for (int mi = 0; mi < 2; mi++) {                                  \
                int c = ks * 2 + achalf;                                      \
                ldmx4(a[mi], (AOFF) + (uint32_t)(arow[mi] * 8 + (c ^ (arow[mi] & 7))) * 16); \
            }                                                                 \
            _Pragma("unroll")                                                 \
            for (int nj = 0; nj < 2; nj++) {                                  \
                int c = ks * 2 + bchalf;                                      \
                ldmx4(b[nj], (BOFF) + (uint32_t)(brow[nj] * 8 + (c ^ (brow[nj] & 7))) * 16); \
            }                                                                 \
            _Pragma("unroll")                                                 \
            for (int mi = 0; mi < 2; mi++)                                    \
                _Pragma("unroll")                                             \
                for (int nt = 0; nt < 4; nt++)                                \
                    mma16816(acc[mi][nt], a[mi], &b[nt >> 1][(nt & 1) * 2]);  \
        }                                                                     \
    } while (0)

    // ---------- prologue ----------
    LOAD_PAIR(0);
    ISSUE_B_PAIR(0, 0); CP_COMMIT();
    ISSUE_B_PAIR(1, 2); CP_COMMIT();
    CONVERT_PAIR(0);
    CP_WAIT1();            // pair 0 B complete (pair 1 still in flight)
    __syncthreads();

    // B ring slot of pair p: (2p) mod 6 -> cycles 0,2,4
    int sB = 0;            // slot of current pair p
    int sBiss = 4;         // slot for pair p+2

    // ---------- main loop: one barrier per PAIR ----------
    for (int p = 0; p < NP; p++) {
        if (p + 1 < NP) LOAD_PAIR(p + 1);
        if (p + 2 < NP) ISSUE_B_PAIR(p + 2, sBiss);
        CP_COMMIT();

        const uint32_t a0 = bAbf + (uint32_t)((2 * p) & 3) * ABF_ST;
        const uint32_t a1 = bAbf + (uint32_t)((2 * p + 1) & 3) * ABF_ST;
        const uint32_t b0 = bB + (uint32_t)sB * B_ST;
        const uint32_t b1 = b0 + B_ST;

        COMPUTE_TILE(a0, b0);                 // tile 2p  (covers LDG latency)
        if (p + 1 < NP) CONVERT_PAIR(p + 1);  // own data; published by sync below
        COMPUTE_TILE(a1, b1);                 // tile 2p+1

        CP_WAIT1();                           // pair p+1 B complete
        __syncthreads();                      // publish A[p+1], B[p+1]; free B[p], A[p]

        sB    = (sB    == 4) ? 0 : sB + 2;
        sBiss = (sBiss == 4) ? 0 : sBiss + 2;
    }

    // ---------- epilogue: -2.5*log10(x) ----------
    const float C = -0.75257498915995302f;   // -2.5 / log2(10)
#pragma unroll
    for (int mi = 0; mi < 2; mi++) {
        const size_t row0 = bm0 + wmBase + mi * 16 + (lane >> 2);
#pragma unroll
        for (int nt = 0; nt < 4; nt++) {
            const int col = wnBase + nt * 8 + (lane & 3) * 2;
            float2 v0, v1;
            v0.x = C * __log2f(acc[mi][nt][0]);
            v0.y = C * __log2f(acc[mi][nt][1]);
            v1.x = C * __log2f(acc[mi][nt][2]);
            v1.y = C * __log2f(acc[mi][nt][3]);
            *reinterpret_cast<float2*>(out + row0 * BN + col)       = v0;
            *reinterpret_cast<float2*>(out + (row0 + 8) * BN + col) = v1;
        }
    }
}

extern "C" void kernel_launch(void* const* d_in, const int* in_sizes, int n_in,
                              void* d_out, int out_size) {
    const float* l_target = (const float*)d_in[0];   // [B, L] fp32
    const float* trans    = (const float*)d_in[1];   // [F, L] fp32
    const float* lam      = (const float*)d_in[2];   // [L]    fp32

    const int L = in_sizes[2];
    const int F = in_sizes[1] / L;   // 128
    const int B = in_sizes[0] / L;   // 8192
    float* out = (float*)d_out;

    cudaFuncSetAttribute(gemm_log_kernel,
                         cudaFuncAttributeMaxDynamicSharedMemorySize, DYN_SMEM);

    int total4 = (F * L) >> 2;
    wt_kernel<<<(total4 + 255) / 256, 256>>>(trans, lam, F, L);
    gemm_log_kernel<<<B / BM, THREADS, DYN_SMEM>>>(l_target, out, L);
}

// round 10
// speedup vs baseline: 1.9491x; 1.2347x over previous
#include <cuda_runtime.h>
#include <cuda_bf16.h>
#include <cstdint>

// out[b,f] = -2.5*log10( sum_l A[b,l] * (trans[f,l]*w[l]) )
// wt_kernel -> g_wt bf16 [F,L] (2MB, L2-resident)
// gemm_log_kernel: R9 core (BM=64 BN=128 BK=64, 32x32 warp tiles, 128B rows,
//   conflict-free swizzle, pair-pipelined cp.async B + LDG->bf16 A, 1 bar/pair)
//   BUT 512 threads: each warp-tile owned by a PAIR of warps splitting the 4
//   K16 steps -> 4 warps/SMSP at UNCHANGED fragment traffic. Final merge of
//   partner accumulators via smem (reuses B ring).
// Ruled out: split-K via gmem (2x), 16-wide warp tiles (frag x1.5), manual
// fragment double-buffering (regs). tcgen05 rejected by ptxas (compute_103).

#define BM 64
#define BN 128
#define BK 64
#define THREADS 512
#define B_ST   16384                 // BN*BK*2
#define ABF_ST 8192                  // BM*BK*2
#define NB_ST  6                     // B ring: 6 tiles (3 pairs)
#define OFF_ABF (NB_ST * B_ST)
#define DYN_SMEM (OFF_ABF + 4 * ABF_ST + 1024)   // 96 + 32 KB

__device__ __align__(16) __nv_bfloat16 g_wt[128 * 8192];

__global__ void wt_kernel(const float* __restrict__ trans,
                          const float* __restrict__ lam, int F, int L) {
    int i4 = blockIdx.x * blockDim.x + threadIdx.x;
    int total = (F * L) >> 2;
    if (i4 >= total) return;
    int l0 = (i4 % (L >> 2)) << 2;
    float4 t = reinterpret_cast<const float4*>(trans)[i4];
    float w[4];
#pragma unroll
    for (int j = 0; j < 4; j++) {
        int l = l0 + j;
        int hi = l + 1 < L ? l + 1 : L - 1;
        int lo = l > 0 ? l - 1 : 0;
        w[j] = 0.5f * (__ldg(lam + hi) - __ldg(lam + lo));
    }
    __nv_bfloat162 p0 = __floats2bfloat162_rn(t.x * w[0], t.y * w[1]);
    __nv_bfloat162 p1 = __floats2bfloat162_rn(t.z * w[2], t.w * w[3]);
    uint2 v = { reinterpret_cast<uint32_t&>(p0), reinterpret_cast<uint32_t&>(p1) };
    reinterpret_cast<uint2*>(g_wt)[i4] = v;
}

__device__ __forceinline__ uint32_t smem_u32(const void* p) {
    uint32_t a;
    asm("{ .reg .u64 t; cvta.to.shared.u64 t, %1; cvt.u32.u64 %0, t; }"
        : "=r"(a) : "l"(p));
    return a;
}
__device__ __forceinline__ void ldmx4(uint32_t* r, uint32_t addr) {
    asm volatile("ldmatrix.sync.aligned.m8n8.x4.shared.b16 {%0,%1,%2,%3}, [%4];\n"
                 : "=r"(r[0]), "=r"(r[1]), "=r"(r[2]), "=r"(r[3]) : "r"(addr));
}
__device__ __forceinline__ void mma16816(float* c, const uint32_t* a, const uint32_t* b) {
    asm volatile("mma.sync.aligned.m16n8k16.row.col.f32.bf16.bf16.f32 "
                 "{%0,%1,%2,%3}, {%4,%5,%6,%7}, {%8,%9}, {%0,%1,%2,%3};\n"
                 : "+f"(c[0]), "+f"(c[1]), "+f"(c[2]), "+f"(c[3])
                 : "r"(a[0]), "r"(a[1]), "r"(a[2]), "r"(a[3]), "r"(b[0]), "r"(b[1]));
}
__device__ __forceinline__ uint32_t packbf2(float x, float y) {
    __nv_bfloat162 h = __floats2bfloat162_rn(x, y);
    return reinterpret_cast<uint32_t&>(h);
}
__device__ __forceinline__ void cp16(uint32_t dst, const void* src) {
    asm volatile("cp.async.cg.shared.global [%0], [%1], 16;"
                 :: "r"(dst), "l"(src) : "memory");
}
#define CP_COMMIT() asm volatile("cp.async.commit_group;" ::: "memory")
#define CP_WAIT1()  asm volatile("cp.async.wait_group 1;" ::: "memory")

__global__ void __launch_bounds__(THREADS, 1)
gemm_log_kernel(const float* __restrict__ A, float* __restrict__ out, int K) {
    extern __shared__ char dynsmem[];
    const uint32_t base = (smem_u32(dynsmem) + 1023) & ~1023u;
    const uint32_t bB   = base;
    const uint32_t bAbf = base + OFF_ABF;

    const int tid  = threadIdx.x;
    const int lane = tid & 31;
    const int warp = tid >> 5;        // 0..15
    const int wt   = warp >> 1;       // warp-tile 0..7
    const int kh   = warp & 1;        // k-half within BK tile
    const size_t bm0 = (size_t)blockIdx.x * BM;
    const int NKT = K / BK;           // 128 tiles
    const int NP  = NKT >> 1;         // 64 pairs

    // ---- A LDG mapping: row ar = tid>>3 (0..63), 8 fp32 at cols 8*(tid&7)
    const int ar = tid >> 3, acg = tid & 7;
    const float4* aSrc4 = reinterpret_cast<const float4*>(A + (bm0 + ar) * (size_t)K)
                        + 2 * acg;
    // bf16 dest: 128B rows, this thread owns chunk acg^(ar&7) (conflict-free)
    const uint32_t abfrel = (uint32_t)ar * 128 + (uint32_t)((acg ^ (ar & 7)) * 16);

    // ---- B cp mapping: 2 chunks/thread/tile, 128B rows (conflict-free)
    uint32_t brel[2];
    const __nv_bfloat16* bsrc[2];
#pragma unroll
    for (int j = 0; j < 2; j++) {
        int id = tid + 512 * j;
        int n = id >> 3, cc = id & 7;
        brel[j] = (uint32_t)(n * 128 + ((cc ^ (n & 7)) * 16));
        bsrc[j] = g_wt + (size_t)n * K + cc * 8;
    }

    // ---- warp-tile grid: 2 M x 4 N, tile 32x32; warp pair splits ks
    const int wmBase = (wt & 1) * 32;
    const int wnBase = (wt >> 1) * 32;
    int arow[2], brow[2];
#pragma unroll
    for (int mi = 0; mi < 2; mi++) arow[mi] = wmBase + mi * 16 + (lane & 15);
#pragma unroll
    for (int nj = 0; nj < 2; nj++) brow[nj] = wnBase + nj * 16 + ((lane >> 4) << 3) + (lane & 7);
    const int achalf = lane >> 4;
    const int bchalf = (lane >> 3) & 1;
    const int ks0 = kh * 2;           // this warp's K16 steps: ks0, ks0+1

    float acc[2][4][4];
#pragma unroll
    for (int i = 0; i < 2; i++)
#pragma unroll
        for (int j = 0; j < 4; j++)
#pragma unroll
            for (int k = 0; k < 4; k++) acc[i][j][k] = 0.f;

    float4 fa[2][2];   // one PAIR of A tiles (8 floats per tile per thread)

#define LOAD_PAIR(P) do {                                                     \
        const float4* _p0 = aSrc4 + (size_t)(2 * (P)) * (BK >> 2);            \
        const float4* _p1 = _p0 + (BK >> 2);                                  \
        fa[0][0] = __ldg(_p0); fa[0][1] = __ldg(_p0 + 1);                     \
        fa[1][0] = __ldg(_p1); fa[1][1] = __ldg(_p1 + 1);                     \
    } while (0)

#define CONVERT_PAIR(P) do {                                                  \
        _Pragma("unroll")                                                     \
        for (int _t = 0; _t < 2; _t++) {                                      \
            const uint32_t _da = bAbf + (uint32_t)(((2 * (P) + _t) & 3)) * ABF_ST; \
            float4 _x = fa[_t][0], _y = fa[_t][1];                            \
            asm volatile("st.shared.v4.b32 [%0], {%1,%2,%3,%4};" ::           \
                "r"(_da + abfrel),                                            \
                "r"(packbf2(_x.x, _x.y)), "r"(packbf2(_x.z, _x.w)),           \
                "r"(packbf2(_y.x, _y.y)), "r"(packbf2(_y.z, _y.w)) : "memory"); \
        }                                                                     \
    } while (0)

#define ISSUE_B_PAIR(P, S0) do {                                              \
        const uint32_t _b0 = bB + (uint32_t)(S0) * B_ST;                      \
        const uint32_t _b1 = _b0 + B_ST;                                      \
        const size_t _o0 = (size_t)(2 * (P)) * BK;                            \
        _Pragma("unroll")                                                     \
        for (int _j = 0; _j < 2; _j++) {                                      \
            cp16(_b0 + brel[_j], bsrc[_j] + _o0);                             \
            cp16(_b1 + brel[_j], bsrc[_j] + _o0 + BK);                        \
        }                                                                     \
    } while (0)

    // compute this warp's 2 K16 steps of one k-tile
#define COMPUTE_TILE(AOFF, BOFF) do {                                         \
        _Pragma("unroll")                                                     \
        for (int _s = 0; _s < 2; _s++) {                                      \
            const int ks = ks0 + _s;                                          \
            uint32_t a[2][4], b[2][4];                                        \
            _Pragma("unroll")                                                 \
            for (int mi = 0; mi < 2; mi++) {                                  \
                int c = ks * 2 + achalf;                                      \
                ldmx4(a[mi], (AOFF) + (uint32_t)(arow[mi] * 8 + (c ^ (arow[mi] & 7))) * 16); \
            }                                                                 \
            _Pragma("unroll")                                                 \
            for (int nj = 0; nj < 2; nj++) {                                  \
                int c = ks * 2 + bchalf;                                      \
                ldmx4(b[nj], (BOFF) + (uint32_t)(brow[nj] * 8 + (c ^ (brow[nj] & 7))) * 16); \
            }                                                                 \
            _Pragma("unroll")                                                 \
            for (int mi = 0; mi < 2; mi++)                                    \
                _Pragma("unroll")                                             \
                for (int nt = 0; nt < 4; nt++)                                \
                    mma16816(acc[mi][nt], a[mi], &b[nt >> 1][(nt & 1) * 2]);  \
        }                                                                     \
    } while (0)

    // ---------- prologue ----------
    LOAD_PAIR(0);
    ISSUE_B_PAIR(0, 0); CP_COMMIT();
    ISSUE_B_PAIR(1, 2); CP_COMMIT();
    CONVERT_PAIR(0);
    CP_WAIT1();            // pair 0 B complete
    __syncthreads();

    int sB = 0, sBiss = 4;

    // ---------- main loop: one barrier per PAIR of k-tiles ----------
    for (int p = 0; p < NP; p++) {
        if (p + 1 < NP) LOAD_PAIR(p + 1);
        if (p + 2 < NP) ISSUE_B_PAIR(p + 2, sBiss);
        CP_COMMIT();

        const uint32_t a0 = bAbf + (uint32_t)((2 * p) & 3) * ABF_ST;
        const uint32_t a1 = bAbf + (uint32_t)((2 * p + 1) & 3) * ABF_ST;
        const uint32_t b0 = bB + (uint32_t)sB * B_ST;
        const uint32_t b1 = b0 + B_ST;

        COMPUTE_TILE(a0, b0);
        if (p + 1 < NP) CONVERT_PAIR(p + 1);
        COMPUTE_TILE(a1, b1);

        CP_WAIT1();
        __syncthreads();

        sB    = (sB    == 4) ? 0 : sB + 2;
        sBiss = (sBiss == 4) ? 0 : sBiss + 2;
    }

    // ---------- merge partner accumulators via smem (reuse B ring) ----------
    // layout: per warp-tile 4KB at bB + wt*4096; element e (0..31) of lane l
    // at e*128 + l*4  (STS.32 conflict-free: 32 lanes consecutive)
    __syncthreads();   // everyone done with B ring
    const uint32_t xb = bB + (uint32_t)wt * 4096 + (uint32_t)lane * 4;
    if (kh == 0) {
#pragma unroll
        for (int mi = 0; mi < 2; mi++)
#pragma unroll
            for (int nt = 0; nt < 4; nt++)
#pragma unroll
                for (int k = 0; k < 4; k++) {
                    const int e = mi * 16 + nt * 4 + k;
                    asm volatile("st.shared.f32 [%0], %1;"
                                 :: "r"(xb + (uint32_t)e * 128), "f"(acc[mi][nt][k])
                                 : "memory");
                }
    }
    __syncthreads();

    if (kh == 1) {
        const float C = -0.75257498915995302f;   // -2.5 / log2(10)
#pragma unroll
        for (int mi = 0; mi < 2; mi++) {
            const size_t row0 = bm0 + wmBase + mi * 16 + (lane >> 2);
#pragma unroll
            for (int nt = 0; nt < 4; nt++) {
                float part[4];
#pragma unroll
                for (int k = 0; k < 4; k++) {
                    const int e = mi * 16 + nt * 4 + k;
                    asm volatile("ld.shared.f32 %0, [%1];"
                                 : "=f"(part[k]) : "r"(xb + (uint32_t)e * 128));
                }
                const int col = wnBase + nt * 8 + (lane & 3) * 2;
                float2 v0, v1;
                v0.x = C * __log2f(acc[mi][nt][0] + part[0]);
                v0.y = C * __log2f(acc[mi][nt][1] + part[1]);
                v1.x = C * __log2f(acc[mi][nt][2] + part[2]);
                v1.y = C * __log2f(acc[mi][nt][3] + part[3]);
                *reinterpret_cast<float2*>(out + row0 * BN + col)       = v0;
                *reinterpret_cast<float2*>(out + (row0 + 8) * BN + col) = v1;
            }
        }
    }
}

extern "C" void kernel_launch(void* const* d_in, const int* in_sizes, int n_in,
                              void* d_out, int out_size) {
    const float* l_target = (const float*)d_in[0];   // [B, L] fp32
    const float* trans    = (const float*)d_in[1];   // [F, L] fp32
    const float* lam      = (const float*)d_in[2];   // [L]    fp32

    const int L = in_sizes[2];
    const int F = in_sizes[1] / L;   // 128
    const int B = in_sizes[0] / L;   // 8192
    float* out = (float*)d_out;

    cudaFuncSetAttribute(gemm_log_kernel,
                         cudaFuncAttributeMaxDynamicSharedMemorySize, DYN_SMEM);

    int total4 = (F * L) >> 2;
    wt_kernel<<<(total4 + 255) / 256, 256>>>(trans, lam, F, L);
    gemm_log_kernel<<<B / BM, THREADS, DYN_SMEM>>>(l_target, out, L);
}